// round 16
// baseline (speedup 1.0000x reference)
#include <cuda_runtime.h>
#include <stdint.h>
#include <math_constants.h>

// ---------------- problem constants ----------------
constexpr int BROWS = 16384;
constexpr int DIN   = 2048;
constexpr int LAT   = 512;
constexpr int KE    = 256;
constexpr int SOMW  = 16;

constexpr size_t OFF_XE   = 0;
constexpr size_t OFF_XQ   = OFF_XE + (size_t)BROWS * DIN;
constexpr size_t OFF_ZE   = OFF_XQ + (size_t)BROWS * DIN;
constexpr size_t OFF_ZQ   = OFF_ZE + (size_t)BROWS * LAT;
constexpr size_t OFF_NB   = OFF_ZQ + (size_t)BROWS * LAT;
constexpr size_t OFF_K    = OFF_NB + (size_t)BROWS * 5 * LAT;
constexpr size_t OFF_DIST = OFF_K  + (size_t)BROWS;

// ---------------- device scratch ----------------
__device__ float g_zsq[BROWS];
__device__ float g_esq[KE];
__device__ float g_U[(size_t)KE * DIN];
__device__ float g_WT[(size_t)LAT * DIN];   // enc_w^T  [512, 2048]
__device__ int   g_k[BROWS];

// ---------------- arch-feature gate ----------------
#if defined(__CUDA_ARCH_FEAT_SM103_ALL) || defined(__CUDA_ARCH_FAMILY_SPECIFIC__) || defined(__CUDA_ARCH_SPECIFIC__)
#define USE_TC 1
#else
#define USE_TC 0
#endif

// ---------------- common helpers ----------------
__device__ __forceinline__ uint32_t smem_u32(const void* p) {
    uint32_t a;
    asm("{ .reg .u64 t; cvta.to.shared.u64 t, %1; cvt.u32.u64 %0, t; }"
        : "=r"(a) : "l"(p));
    return a;
}
__device__ __forceinline__ float ftr(float x) {
    return __uint_as_float(__float_as_uint(x) & 0xFFFFE000u);
}
#define SW128(o) ((o) ^ (((o) >> 3) & 0x70))

__device__ __forceinline__ void cp16(uint32_t dst, const float* src) {
    asm volatile("cp.async.cg.shared.global [%0], [%1], 16;"
                 :: "r"(dst), "l"((unsigned long long)__cvta_generic_to_global(src))
                 : "memory");
}
__device__ __forceinline__ void cp_commit() {
    asm volatile("cp.async.commit_group;" ::: "memory");
}
__device__ __forceinline__ void cp_wait1() {
    asm volatile("cp.async.wait_group 1;" ::: "memory");
}
__device__ __forceinline__ void mma8(float* c, const uint32_t* a, const uint32_t* b) {
    asm volatile(
        "mma.sync.aligned.m16n8k8.row.col.f32.tf32.tf32.f32 "
        "{%0,%1,%2,%3}, {%4,%5,%6,%7}, {%8,%9}, {%0,%1,%2,%3};\n"
        : "+f"(c[0]), "+f"(c[1]), "+f"(c[2]), "+f"(c[3])
        : "r"(a[0]), "r"(a[1]), "r"(a[2]), "r"(a[3]), "r"(b[0]), "r"(b[1]));
}

#if USE_TC
// ---------------- tcgen05 helpers ----------------
constexpr uint64_t DESC_BASE =
    (uint64_t(2) << 61) | (uint64_t(1) << 46) | (uint64_t(64) << 32) | (uint64_t(1) << 16);
__device__ __forceinline__ uint64_t mkdesc(uint32_t addr) {
    return DESC_BASE | ((uint64_t)(addr >> 4) & 0x3FFF);
}
constexpr uint32_t IDESC_TF32 =
    (1u << 4) | (2u << 7) | (2u << 10) | ((128u / 8) << 17) | ((128u / 16) << 24);
constexpr uint32_t IDESC_TF32_N256 =
    (1u << 4) | (2u << 7) | (2u << 10) | ((256u / 8) << 17) | ((128u / 16) << 24);

__device__ __forceinline__ void mbar_init(uint32_t a, uint32_t cnt) {
    asm volatile("mbarrier.init.shared.b64 [%0], %1;" :: "r"(a), "r"(cnt) : "memory");
}
__device__ __forceinline__ void mbar_arrive(uint32_t a) {
    asm volatile("mbarrier.arrive.shared.b64 _, [%0];" :: "r"(a) : "memory");
}
__device__ __forceinline__ void mbar_wait(uint32_t a, uint32_t ph) {
    asm volatile(
        "{\n\t.reg .pred P;\n\t"
        "W_%=: mbarrier.try_wait.parity.acquire.cta.shared::cta.b64 P, [%0], %1, 0x989680;\n\t"
        "@P bra D_%=;\n\t"
        "bra W_%=;\n\t"
        "D_%=:\n\t}"
        :: "r"(a), "r"(ph) : "memory");
}
__device__ __forceinline__ void tc_alloc(uint32_t dst_smem, uint32_t ncols) {
    asm volatile("tcgen05.alloc.cta_group::1.sync.aligned.shared::cta.b32 [%0], %1;"
                 :: "r"(dst_smem), "r"(ncols) : "memory");
}
__device__ __forceinline__ void tc_relinq() {
    asm volatile("tcgen05.relinquish_alloc_permit.cta_group::1.sync.aligned;");
}
__device__ __forceinline__ void tc_dealloc(uint32_t tmem, uint32_t ncols) {
    asm volatile("tcgen05.dealloc.cta_group::1.sync.aligned.b32 %0, %1;" :: "r"(tmem), "r"(ncols));
}
__device__ __forceinline__ void tc_commit(uint32_t mbar) {
    asm volatile("tcgen05.commit.cta_group::1.mbarrier::arrive::one.shared::cluster.b64 [%0];"
                 :: "r"(mbar) : "memory");
}
__device__ __forceinline__ void mma_tf32i(uint32_t d, uint64_t ad, uint64_t bd,
                                          uint32_t idesc, uint32_t en) {
    asm volatile(
        "{\n\t.reg .pred p;\n\t"
        "setp.ne.u32 p, %4, 0;\n\t"
        "tcgen05.mma.cta_group::1.kind::tf32 [%0], %1, %2, %3, {%5,%5,%5,%5}, p;\n\t}"
        :: "r"(d), "l"(ad), "l"(bd), "r"(idesc), "r"(en), "r"(0u) : "memory");
}
__device__ __forceinline__ void mma_tf32(uint32_t d, uint64_t ad, uint64_t bd, uint32_t en) {
    mma_tf32i(d, ad, bd, IDESC_TF32, en);
}
__device__ __forceinline__ void fence_async() {
    asm volatile("fence.proxy.async.shared::cta;" ::: "memory");
}
__device__ __forceinline__ void tc_fence_after() {
    asm volatile("tcgen05.fence::after_thread_sync;" ::: "memory");
}
__device__ __forceinline__ void tc_wait_ld() {
    asm volatile("tcgen05.wait::ld.sync.aligned;" ::: "memory");
}
__device__ __forceinline__ void ldtm32(uint32_t* r, uint32_t tmem) {
    asm volatile(
        "tcgen05.ld.sync.aligned.32x32b.x32.b32 "
        "{%0,%1,%2,%3,%4,%5,%6,%7,%8,%9,%10,%11,%12,%13,%14,%15,"
        "%16,%17,%18,%19,%20,%21,%22,%23,%24,%25,%26,%27,%28,%29,%30,%31}, [%32];"
        : "=r"(r[0]), "=r"(r[1]), "=r"(r[2]), "=r"(r[3]), "=r"(r[4]), "=r"(r[5]),
          "=r"(r[6]), "=r"(r[7]), "=r"(r[8]), "=r"(r[9]), "=r"(r[10]), "=r"(r[11]),
          "=r"(r[12]), "=r"(r[13]), "=r"(r[14]), "=r"(r[15]), "=r"(r[16]), "=r"(r[17]),
          "=r"(r[18]), "=r"(r[19]), "=r"(r[20]), "=r"(r[21]), "=r"(r[22]), "=r"(r[23]),
          "=r"(r[24]), "=r"(r[25]), "=r"(r[26]), "=r"(r[27]), "=r"(r[28]), "=r"(r[29]),
          "=r"(r[30]), "=r"(r[31])
        : "r"(tmem));
}
#endif  // USE_TC

// ---------------- smem geometry ----------------
// 288-thread dist kernel
constexpr int GSMEM1 = 73728;
// N256 x_e kernel (2-pass + staging)
constexpr int NSTR256 = 260;
constexpr int NSTG256 = 32 * NSTR256 * 4;     // 33280
constexpr int GSMEMN = 2048 + 2 * 65536 + 2 * NSTG256;   // 199680
// N256 z_e / U kernel (3-pass, staging-free; buf = AH16K|AL16K|BH32K|BL32K)
constexpr int GSMEMZ = 2048 + 2 * 98304;      // 198656

// =====================================================================
// transpose_w: WT[n][k] = W[k][n]   (exact copy, bit-identical values)
// =====================================================================
__global__ void transpose_w(const float* __restrict__ W, float* __restrict__ WT,
                            int K, int N)
{
    __shared__ float tile[32][33];
    const int n0 = blockIdx.x * 32, k0 = blockIdx.y * 32;
    const int tx = threadIdx.x, ty = threadIdx.y;
#pragma unroll
    for (int i = ty; i < 32; i += 8)
        tile[i][tx] = W[(size_t)(k0 + i) * N + n0 + tx];
    __syncthreads();
#pragma unroll
    for (int i = ty; i < 32; i += 8)
        WT[(size_t)(n0 + i) * K + k0 + tx] = tile[tx][i];
}

// =====================================================================
// gemm_ze: 128x256 tile, 3-pass (split A and B), B pre-transposed [N,K].
// 544 threads: 512 producers + issuer. Used for z_e and U.
// C = A[M,K] @ BT[N,K]^T + bias
// =====================================================================
__global__ __launch_bounds__(544, 1) void gemm_ze(
    const float* __restrict__ A, const float* __restrict__ BT,
    const float* __restrict__ bias, float* __restrict__ C,
    int M, int N, int K)
{
#if USE_TC
    constexpr int NBUF = 2;
    constexpr int BUFB = 98304;       // AH 16K | AL 16K | BH 32K | BL 32K
    constexpr int ALO  = 16384;
    constexpr int BHI  = 32768;
    constexpr int BLO  = 65536;

    extern __shared__ char smem[];
    const uint32_t sb = smem_u32(smem);
    const uint32_t ab0 = (sb + 1152u) & ~1023u;
    char* const base = smem + (ab0 - sb);

    const int tid = threadIdx.x, lane = tid & 31, warp = tid >> 5;
    const int m0 = blockIdx.y * 128, n1 = blockIdx.x * 256;

    const uint32_t FUL = sb + 8, EMP = sb + 24, DON = sb + 40;

    if (warp == 0) { tc_alloc(sb, 256); tc_relinq(); }
    if (tid == 0) {
#pragma unroll
        for (int s = 0; s < NBUF; s++) {
            mbar_init(FUL + s * 8, 16);
            mbar_init(EMP + s * 8, 1);
        }
        mbar_init(DON, 1);
    }
    __syncthreads();
    const uint32_t tmem = *(const uint32_t*)smem;
    const int nch = K / 32;

    if (tid < 512) {
        // ---- producers ----
        const int arow = tid >> 2, acolb = (tid & 3) * 8;   // A: 128 rows, 8 f/thr
        const int brow = tid >> 1, bcolb = (tid & 1) * 16;  // B: 256 rows, 16 f/thr

        float4 ar[2][2], br[2][4];

        auto fetch = [&](int c, int s) {
            const float* ap = A + (size_t)(m0 + arow) * K + c * 32 + acolb;
            ar[s][0] = *(const float4*)ap;
            ar[s][1] = *(const float4*)(ap + 4);
            const float* bp = BT + (size_t)(n1 + brow) * K + c * 32 + bcolb;
#pragma unroll
            for (int q = 0; q < 4; q++) br[s][q] = *(const float4*)(bp + q * 4);
        };

        fetch(0, 0);
        if (nch > 1) fetch(1, 1);

        for (int c = 0; c < nch; c++) {
            const int s = c & 1;
            char* const AHp = base + s * BUFB;
            if (c >= NBUF) mbar_wait(EMP + s * 8, (uint32_t)((c / NBUF - 1) & 1));

            // A STS hi/lo
#pragma unroll
            for (int q = 0; q < 2; q++) {
                float4 v = ar[s][q];
                const uint32_t sw = SW128((uint32_t)(arow * 128 + (acolb + q * 4) * 4));
                float4 h, l;
                h.x = ftr(v.x); h.y = ftr(v.y); h.z = ftr(v.z); h.w = ftr(v.w);
                l.x = v.x - h.x; l.y = v.y - h.y; l.z = v.z - h.z; l.w = v.w - h.w;
                *(float4*)(AHp + sw) = h;
                *(float4*)(AHp + ALO + sw) = l;
            }
            // B STS hi/lo
#pragma unroll
            for (int q = 0; q < 4; q++) {
                float4 v = br[s][q];
                const uint32_t sw = SW128((uint32_t)(brow * 128 + (bcolb + q * 4) * 4));
                float4 h, l;
                h.x = ftr(v.x); h.y = ftr(v.y); h.z = ftr(v.z); h.w = ftr(v.w);
                l.x = v.x - h.x; l.y = v.y - h.y; l.z = v.z - h.z; l.w = v.w - h.w;
                *(float4*)(AHp + BHI + sw) = h;
                *(float4*)(AHp + BLO + sw) = l;
            }

            if (c + 2 < nch) fetch(c + 2, s);
            fence_async();
            __syncwarp();
            if (lane == 0) mbar_arrive(FUL + s * 8);
        }
    } else if (tid == 512) {
        // ---- MMA issuer ----
        for (int c = 0; c < nch; c++) {
            const int s = c & 1;
            mbar_wait(FUL + s * 8, (uint32_t)((c / NBUF) & 1));
            const uint32_t AHu = ab0 + s * BUFB;
            const uint64_t adh = mkdesc(AHu), adl = mkdesc(AHu + ALO);
            const uint64_t bdh = mkdesc(AHu + BHI), bdl = mkdesc(AHu + BLO);
#pragma unroll
            for (int ks = 0; ks < 4; ks++) {
                const uint64_t o = ks * 2;
                const uint32_t en0 = (c == 0 && ks == 0) ? 0u : 1u;
                mma_tf32i(tmem, adh + o, bdl + o, IDESC_TF32_N256, en0);
                mma_tf32i(tmem, adl + o, bdh + o, IDESC_TF32_N256, 1u);
                mma_tf32i(tmem, adh + o, bdh + o, IDESC_TF32_N256, 1u);
            }
            tc_commit(c == nch - 1 ? DON : (EMP + s * 8));
        }
    }

    mbar_wait(DON, 0u);
    tc_fence_after();

    if (warp < 4) {
        const int row = m0 + warp * 32 + lane;
#pragma unroll
        for (int cb = 0; cb < 256; cb += 32) {
            uint32_t r[32];
            ldtm32(r, tmem + cb);
            tc_wait_ld();
            float* dst = C + (size_t)row * N + n1 + cb;
            const float4* b4 = (const float4*)(bias + n1 + cb);
#pragma unroll
            for (int q = 0; q < 8; q++) {
                float4 b = b4[q];
                float4 v;
                v.x = __uint_as_float(r[q * 4 + 0]) + b.x;
                v.y = __uint_as_float(r[q * 4 + 1]) + b.y;
                v.z = __uint_as_float(r[q * 4 + 2]) + b.z;
                v.w = __uint_as_float(r[q * 4 + 3]) + b.w;
                *(float4*)(dst + q * 4) = v;
            }
        }
    }
    __syncthreads();
    if (warp == 0) tc_dealloc(tmem, 256);

#else
    // ---- fallback: SIMT correct (non-a pass; never runs on target) ----
    const int tid = threadIdx.x;
    const int m0 = blockIdx.y * 128, n1 = blockIdx.x * 256;
    for (int idx = tid; idx < 128 * 256; idx += 544) {
        const int m = m0 + (idx >> 8);
        const int n = n1 + (idx & 255);
        float s = 0.f;
        const float* a = A + (size_t)m * K;
        const float* b = BT + (size_t)n * K;
        for (int k = 0; k < K; k++) s = fmaf(a[k], b[k], s);
        C[(size_t)m * N + n] = s + bias[n];
    }
#endif
}

// =====================================================================
// gemm_n256: 128x256 tile, 2-pass (split A), staged B transpose. x_e only.
// =====================================================================
__global__ __launch_bounds__(544, 1) void gemm_n256(
    const float* __restrict__ A, const float* __restrict__ B,
    const float* __restrict__ bias, float* __restrict__ C,
    int M, int N, int K)
{
#if USE_TC
    constexpr int NBUF = 2;
    constexpr int BUFB = 65536;
    constexpr int ALO  = 16384;
    constexpr int BHI  = 32768;

    extern __shared__ char smem[];
    const uint32_t sb = smem_u32(smem);
    const uint32_t ab0 = (sb + 1152u) & ~1023u;
    char* const base = smem + (ab0 - sb);
    const uint32_t stg_u = ab0 + NBUF * BUFB;
    char* const stg = base + NBUF * BUFB;

    const int tid = threadIdx.x, lane = tid & 31, warp = tid >> 5;
    const int m0 = blockIdx.y * 128, n1 = blockIdx.x * 256;

    const uint32_t FUL = sb + 8, EMP = sb + 24, DON = sb + 40;

    if (warp == 0) { tc_alloc(sb, 256); tc_relinq(); }
    if (tid == 0) {
#pragma unroll
        for (int s = 0; s < NBUF; s++) {
            mbar_init(FUL + s * 8, 16);
            mbar_init(EMP + s * 8, 1);
        }
        mbar_init(DON, 1);
    }
    __syncthreads();
    const uint32_t tmem = *(const uint32_t*)smem;
    const int nch = K / 32;

    if (tid < 512) {
        const int arow = tid >> 2, acolb = (tid & 3) * 8;
        const int krow = tid >> 4, nseg = (tid & 15) * 16;
        const int bn = tid & 255, kq = tid >> 8;

        float4 a0[2], a1[2];

        auto fetchA = [&](int c, float4 (&ar)[2]) {
            const float* ap = A + (size_t)(m0 + arow) * K + c * 32 + acolb;
            ar[0] = *(const float4*)ap;
            ar[1] = *(const float4*)(ap + 4);
        };
        auto issueB = [&](int c) {
            const uint32_t d = stg_u + (c & 1) * NSTG256 + (krow * NSTR256 + nseg) * 4;
            const float* src = B + (size_t)(c * 32 + krow) * N + n1 + nseg;
#pragma unroll
            for (int j = 0; j < 4; j++) cp16(d + j * 16, src + j * 4);
        };

        fetchA(0, a0);
        if (nch > 1) fetchA(1, a1);
        issueB(0); cp_commit();
        if (nch > 1) { issueB(1); cp_commit(); }

        for (int c = 0; c < nch; c++) {
            const int s = c & 1;
            char* const AHp = base + s * BUFB;
            if (c >= NBUF) mbar_wait(EMP + s * 8, (uint32_t)((c / NBUF - 1) & 1));

            cp_wait1();
            asm volatile("bar.sync 1, 512;" ::: "memory");

            const float* sg = (const float*)(stg + (c & 1) * NSTG256);
            float bv[16];
#pragma unroll
            for (int j = 0; j < 16; j++)
                bv[j] = sg[(kq * 16 + j) * NSTR256 + bn];

            asm volatile("bar.sync 1, 512;" ::: "memory");
            if (c + 2 < nch) issueB(c + 2);
            cp_commit();

#pragma unroll
            for (int q = 0; q < 4; q++) {
                const uint32_t off = (uint32_t)(bn * 128 + kq * 64 + q * 16);
                *(float4*)(AHp + BHI + SW128(off)) = *(float4*)&bv[q * 4];
            }

            float4* const asrc = (c & 1) ? a1 : a0;
#pragma unroll
            for (int q = 0; q < 2; q++) {
                float4 v = asrc[q];
                const uint32_t sw = SW128((uint32_t)(arow * 128 + (acolb + q * 4) * 4));
                float4 h, l;
                h.x = ftr(v.x); h.y = ftr(v.y); h.z = ftr(v.z); h.w = ftr(v.w);
                l.x = v.x - h.x; l.y = v.y - h.y; l.z = v.z - h.z; l.w = v.w - h.w;
                *(float4*)(AHp + sw) = h;
                *(float4*)(AHp + ALO + sw) = l;
            }

            if (c + 2 < nch) fetchA(c + 2, (c & 1) ? a1 : a0);
            fence_async();
            __syncwarp();
            if (lane == 0) mbar_arrive(FUL + s * 8);
        }
    } else if (tid == 512) {
        for (int c = 0; c < nch; c++) {
            const int s = c & 1;
            mbar_wait(FUL + s * 8, (uint32_t)((c / NBUF) & 1));
            const uint32_t AHu = ab0 + s * BUFB;
            const uint64_t adh = mkdesc(AHu), adl = mkdesc(AHu + ALO);
            const uint64_t bdh = mkdesc(AHu + BHI);
#pragma unroll
            for (int ks = 0; ks < 4; ks++) {
                const uint64_t o = ks * 2;
                const uint32_t en0 = (c == 0 && ks == 0) ? 0u : 1u;
                mma_tf32i(tmem, adl + o, bdh + o, IDESC_TF32_N256, en0);
                mma_tf32i(tmem, adh + o, bdh + o, IDESC_TF32_N256, 1u);
            }
            tc_commit(c == nch - 1 ? DON : (EMP + s * 8));
        }
    }

    mbar_wait(DON, 0u);
    tc_fence_after();

    if (warp < 4) {
        const int row = m0 + warp * 32 + lane;
#pragma unroll
        for (int cb = 0; cb < 256; cb += 32) {
            uint32_t r[32];
            ldtm32(r, tmem + cb);
            tc_wait_ld();
            float* dst = C + (size_t)row * N + n1 + cb;
            const float4* b4 = (const float4*)(bias + n1 + cb);
#pragma unroll
            for (int q = 0; q < 8; q++) {
                float4 b = b4[q];
                float4 v;
                v.x = __uint_as_float(r[q * 4 + 0]) + b.x;
                v.y = __uint_as_float(r[q * 4 + 1]) + b.y;
                v.z = __uint_as_float(r[q * 4 + 2]) + b.z;
                v.w = __uint_as_float(r[q * 4 + 3]) + b.w;
                *(float4*)(dst + q * 4) = v;
            }
        }
    }
    __syncthreads();
    if (warp == 0) tc_dealloc(tmem, 256);

#else
    const int tid = threadIdx.x;
    const int m0 = blockIdx.y * 128, n1 = blockIdx.x * 256;
    for (int idx = tid; idx < 128 * 256; idx += 544) {
        const int m = m0 + (idx >> 8);
        const int n = n1 + (idx & 255);
        float s = 0.f;
        const float* a = A + (size_t)m * K;
        for (int k = 0; k < K; k++) s = fmaf(a[k], B[(size_t)k * N + n], s);
        C[(size_t)m * N + n] = s + bias[n];
    }
#endif
}

// =====================================================================
// gemm_dist: 288 threads, 2 CTA/SM, 1-pass MODE 1 — R15 verbatim
// =====================================================================
__global__ __launch_bounds__(288, 2) void gemm_dist(
    const float* __restrict__ A, const float* __restrict__ B,
    float* __restrict__ C, int M, int N, int K)
{
#if USE_TC
    constexpr int NBUF = 2;
    constexpr int BUFB = 32768;
    constexpr int BHI  = 16384;

    extern __shared__ char smem[];
    const uint32_t sb = smem_u32(smem);
    const uint32_t ab0 = (sb + 1152u) & ~1023u;
    char* const base = smem + (ab0 - sb);

    const int tid = threadIdx.x, lane = tid & 31, warp = tid >> 5;
    const int m0 = blockIdx.y * 128, n0 = blockIdx.x * 128;

    const uint32_t FUL = sb + 8, EMP = sb + 24, DON = sb + 40;

    if (warp == 0) { tc_alloc(sb, 128); tc_relinq(); }
    if (tid == 0) {
#pragma unroll
        for (int s = 0; s < NBUF; s++) {
            mbar_init(FUL + s * 8, 8);
            mbar_init(EMP + s * 8, 1);
        }
        mbar_init(DON, 1);
    }
    __syncthreads();
    const uint32_t tmem = *(const uint32_t*)smem;
    const int nch = K / 32;

    if (tid < 256) {
        const int arow = tid >> 1, acolb = (tid & 1) * 16;
        float4 ar[2][4], br[2][4];

        auto fetch = [&](int c, int s) {
            const float* ap = A + (size_t)(m0 + arow) * K + c * 32 + acolb;
#pragma unroll
            for (int q = 0; q < 4; q++) ar[s][q] = *(const float4*)(ap + q * 4);
            const float* bp = B + (size_t)(n0 + arow) * K + c * 32 + acolb;
#pragma unroll
            for (int q = 0; q < 4; q++) br[s][q] = *(const float4*)(bp + q * 4);
        };

        fetch(0, 0);
        if (nch > 1) fetch(1, 1);

        for (int c = 0; c < nch; c++) {
            const int s = c & 1;
            char* const AHp = base + s * BUFB;
            if (c >= NBUF) mbar_wait(EMP + s * 8, (uint32_t)((c / NBUF - 1) & 1));

#pragma unroll
            for (int q = 0; q < 4; q++) {
                const uint32_t sw = SW128((uint32_t)(arow * 128 + acolb * 4 + q * 16));
                *(float4*)(AHp + BHI + sw) = br[s][q];
                *(float4*)(AHp + sw) = ar[s][q];
            }
            if (c + 2 < nch) fetch(c + 2, s);
            fence_async();
            __syncwarp();
            if (lane == 0) mbar_arrive(FUL + s * 8);
        }
    } else if (tid == 256) {
        for (int c = 0; c < nch; c++) {
            const int s = c & 1;
            mbar_wait(FUL + s * 8, (uint32_t)((c / NBUF) & 1));
            const uint32_t AHu = ab0 + s * BUFB;
            const uint64_t adh = mkdesc(AHu), bdh = mkdesc(AHu + BHI);
#pragma unroll
            for (int ks = 0; ks < 4; ks++) {
                const uint64_t o = ks * 2;
                mma_tf32(tmem, adh + o, bdh + o, (c == 0 && ks == 0) ? 0u : 1u);
            }
            tc_commit(c == nch - 1 ? DON : (EMP + s * 8));
        }
    }

    mbar_wait(DON, 0u);
    tc_fence_after();

    if (warp < 4) {
        const int row = m0 + warp * 32 + lane;
#pragma unroll
        for (int cb = 0; cb < 128; cb += 32) {
            uint32_t r[32];
            ldtm32(r, tmem + cb);
            tc_wait_ld();
            float* dst = C + (size_t)row * N + n0 + cb;
            const float zs = g_zsq[row];
            const float4* e4 = (const float4*)(g_esq + n0 + cb);
#pragma unroll
            for (int q = 0; q < 8; q++) {
                float4 e = e4[q];
                float4 v;
                v.x = (zs - 2.f * __uint_as_float(r[q * 4 + 0])) + e.x;
                v.y = (zs - 2.f * __uint_as_float(r[q * 4 + 1])) + e.y;
                v.z = (zs - 2.f * __uint_as_float(r[q * 4 + 2])) + e.z;
                v.w = (zs - 2.f * __uint_as_float(r[q * 4 + 3])) + e.w;
                *(float4*)(dst + q * 4) = v;
            }
        }
    }
    __syncthreads();
    if (warp == 0) tc_dealloc(tmem, 128);

#else
    const int tid = threadIdx.x;
    const int m0 = blockIdx.y * 128, n0 = blockIdx.x * 128;
    for (int idx = tid; idx < 128 * 128; idx += 288) {
        const int m = m0 + (idx >> 7);
        const int n = n0 + (idx & 127);
        float t = 0.f;
        const float* a = A + (size_t)m * K;
        const float* b = B + (size_t)n * K;
        for (int k = 0; k < K; k++) t = fmaf(a[k], b[k], t);
        C[(size_t)m * N + n] = (g_zsq[m] - 2.f * t) + g_esq[n];
    }
#endif
}

// ---------------- per-row sum of squares, fp64 accumulate -> fp32 ----------------
__global__ void rowsq_kernel(const float* __restrict__ Z, float* __restrict__ out,
                             int rows, int cols)
{
    int row = blockIdx.x * (blockDim.x >> 5) + (threadIdx.x >> 5);
    int lane = threadIdx.x & 31;
    if (row >= rows) return;
    const float* z = Z + (size_t)row * cols;
    double s = 0.0;
    for (int j = lane; j < cols; j += 32) {
        double v = (double)z[j];
        s += v * v;
    }
#pragma unroll
    for (int o = 16; o > 0; o >>= 1) s += __shfl_xor_sync(0xffffffffu, s, o);
    if (lane == 0) out[row] = (float)s;
}

// ---------------- fused top-4 + fp64 refine -> k ----------------
__global__ __launch_bounds__(128) void refine_kernel(
    const float* __restrict__ dist, const float* __restrict__ ZE,
    const float* __restrict__ emb, float* __restrict__ out)
{
    const int row = blockIdx.x;
    const int t = threadIdx.x;
    const int w = t >> 5;
    const int lane = t & 31;

    __shared__ float sv[128];
    __shared__ int   si[128];
    __shared__ int   cand4[4];
    __shared__ float cv[4];
    __shared__ int   ci[4];

    float d0 = dist[(size_t)row * KE + t];
    float d1 = dist[(size_t)row * KE + t + 128];

#pragma unroll
    for (int r = 0; r < 4; r++) {
        float v; int idx;
        if (d0 <= d1) { v = d0; idx = t; }
        else          { v = d1; idx = t + 128; }
        sv[t] = v; si[t] = idx;
        __syncthreads();
#pragma unroll
        for (int s = 64; s > 0; s >>= 1) {
            if (t < s) {
                float v2 = sv[t + s]; int i2 = si[t + s];
                if (v2 < sv[t] || (v2 == sv[t] && i2 < si[t])) { sv[t] = v2; si[t] = i2; }
            }
            __syncthreads();
        }
        const int win = si[0];
        if (t == 0) cand4[r] = win;
        if (win == t) d0 = CUDART_INF_F;
        else if (win == t + 128) d1 = CUDART_INF_F;
        __syncthreads();
    }

    const int cand = cand4[w];
    const float* z = ZE + (size_t)row * LAT;
    const float* e = emb + (size_t)cand * LAT;

    double s = 0.0;
    for (int j = lane; j < LAT; j += 32)
        s += (double)z[j] * (double)e[j];
#pragma unroll
    for (int o = 16; o > 0; o >>= 1) s += __shfl_xor_sync(0xffffffffu, s, o);

    if (lane == 0) {
        float tt = (float)s;
        float a = g_zsq[row] - 2.f * tt;
        float d = a + g_esq[cand];
        cv[w] = d;
        ci[w] = cand;
    }
    __syncthreads();

    if (t == 0) {
        float bv = cv[0]; int bi = ci[0];
#pragma unroll
        for (int r = 1; r < 4; r++) {
            float v = cv[r]; int i = ci[r];
            if (v < bv || (v == bv && i < bi)) { bv = v; bi = i; }
        }
        g_k[row] = bi;
        out[OFF_K + row] = (float)bi;
    }
}

// ---------------- fused gathers (float4): z_q, neighbors, x_q ----------------
__global__ __launch_bounds__(128) void gather_all_kernel(
    const float* __restrict__ emb, float* __restrict__ out)
{
    const int row = blockIdx.x;
    const int t = threadIdx.x;
    const int k = g_k[row];

    const int k1 = k / SOMW;
    const int k2 = k % SOMW;
    const float4* s0 = (const float4*)(emb + (size_t)k * LAT);
    const float4* s1 = (k1 < SOMW - 1) ? (const float4*)(emb + (size_t)(k + SOMW) * LAT) : nullptr;
    const float4* s2 = (k1 > 0)        ? (const float4*)(emb + (size_t)(k - SOMW) * LAT) : nullptr;
    const float4* s4 = (k2 > 0)        ? (const float4*)(emb + (size_t)(k - 1) * LAT)    : nullptr;
    const float4 zero = make_float4(0.f, 0.f, 0.f, 0.f);

    float4* zq = (float4*)(out + OFF_ZQ + (size_t)row * LAT);
    float4* nb = (float4*)(out + OFF_NB + (size_t)row * 5 * LAT);

    float4 v0 = s0[t];
    zq[t] = v0;
    nb[t] = v0;
    nb[128 + t] = s1 ? s1[t] : zero;
    nb[256 + t] = s2 ? s2[t] : zero;
    nb[384 + t] = zero;                  // right (faithful bug: always 0)
    nb[512 + t] = s4 ? s4[t] : zero;

    const float4* us = (const float4*)(g_U + (size_t)k * DIN);
    float4* xq = (float4*)(out + OFF_XQ + (size_t)row * DIN);
#pragma unroll
    for (int i = t; i < DIN / 4; i += 128)
        xq[i] = us[i];
}

// =====================================================================
extern "C" void kernel_launch(void* const* d_in, const int* in_sizes, int n_in,
                              void* d_out, int out_size)
{
    const float* x       = (const float*)d_in[0];
    const float* enc_w   = (const float*)d_in[1];
    const float* enc_b   = (const float*)d_in[2];
    const float* dec_q_w = (const float*)d_in[3];
    const float* dec_q_b = (const float*)d_in[4];
    const float* dec_e_w = (const float*)d_in[5];
    const float* dec_e_b = (const float*)d_in[6];
    const float* emb     = (const float*)d_in[7];
    float* out = (float*)d_out;

    float* zsq_p; cudaGetSymbolAddress((void**)&zsq_p, g_zsq);
    float* esq_p; cudaGetSymbolAddress((void**)&esq_p, g_esq);
    float* U_p;   cudaGetSymbolAddress((void**)&U_p,   g_U);
    float* WT_p;  cudaGetSymbolAddress((void**)&WT_p,  g_WT);

    cudaFuncSetAttribute(gemm_ze, cudaFuncAttributeMaxDynamicSharedMemorySize, GSMEMZ);
    cudaFuncSetAttribute(gemm_n256, cudaFuncAttributeMaxDynamicSharedMemorySize, GSMEMN);
    cudaFuncSetAttribute(gemm_dist, cudaFuncAttributeMaxDynamicSharedMemorySize, GSMEM1);

    // launch 0: e_sq
    rowsq_kernel<<<KE / 8, 256>>>(emb, esq_p, KE, LAT);

    // launch 1: WT = enc_w^T (exact copy)
    transpose_w<<<dim3(LAT / 32, DIN / 32), dim3(32, 8)>>>(enc_w, WT_p, DIN, LAT);

    // launch 2: z_e = x @ enc_w + enc_b  (3-pass, N256, staging-free via WT)
    gemm_ze<<<dim3(LAT / 256, BROWS / 128), 544, GSMEMZ>>>(
        x, WT_p, enc_b, out + OFF_ZE, BROWS, LAT, DIN);

    // launch 3 (ncu capture slot): x_e (2-pass, 128x256 tile)
    gemm_n256<<<dim3(DIN / 256, BROWS / 128), 544, GSMEMN>>>(
        out + OFF_ZE, dec_e_w, dec_e_b, out + OFF_XE, BROWS, DIN, LAT);

    // launch 4: z_sq
    rowsq_kernel<<<BROWS / 8, 256>>>(out + OFF_ZE, zsq_p, BROWS, LAT);

    // launch 5: U = emb_flat @ dec_q_w + dec_q_b  (3-pass N256 via dec_q_w^T?
    //           dec_q_w is [LAT, DIN] K-major; use gemm_n256-style staging? No —
    //           reuse gemm_ze with a transpose of dec_q_w)
    //           U is tiny (0.5 GF): transpose dec_q_w then gemm_ze.
    {
        // reuse g_WT? No - g_WT holds enc_w^T needed only by launch 2 (done).
        transpose_w<<<dim3(DIN / 32, LAT / 32), dim3(32, 8)>>>(dec_q_w, WT_p, LAT, DIN);
        gemm_ze<<<dim3(DIN / 256, KE / 128), 544, GSMEMZ>>>(
            emb, WT_p, dec_q_b, U_p, KE, DIN, LAT);
    }

    // launch 7: z_dist_flat (1-pass, 2 CTA/SM; argmin protected by refine)
    gemm_dist<<<dim3(KE / 128, BROWS / 128), 288, GSMEM1>>>(
        out + OFF_ZE, emb, out + OFF_DIST, BROWS, KE, LAT);

    // launch 8: fused top-4 + fp64 refine -> k
    refine_kernel<<<BROWS, 128>>>(out + OFF_DIST, out + OFF_ZE, emb, out);

    // launch 9: fused gathers (float4)
    gather_all_kernel<<<BROWS, 128>>>(emb, out);
}

// round 17
// speedup vs baseline: 1.0114x; 1.0114x over previous
#include <cuda_runtime.h>
#include <stdint.h>
#include <math_constants.h>

// ---------------- problem constants ----------------
constexpr int BROWS = 16384;
constexpr int DIN   = 2048;
constexpr int LAT   = 512;
constexpr int KE    = 256;
constexpr int SOMW  = 16;

constexpr size_t OFF_XE   = 0;
constexpr size_t OFF_XQ   = OFF_XE + (size_t)BROWS * DIN;
constexpr size_t OFF_ZE   = OFF_XQ + (size_t)BROWS * DIN;
constexpr size_t OFF_ZQ   = OFF_ZE + (size_t)BROWS * LAT;
constexpr size_t OFF_NB   = OFF_ZQ + (size_t)BROWS * LAT;
constexpr size_t OFF_K    = OFF_NB + (size_t)BROWS * 5 * LAT;
constexpr size_t OFF_DIST = OFF_K  + (size_t)BROWS;

// ---------------- device scratch ----------------
__device__ float g_zsq[BROWS];
__device__ float g_esq[KE];
__device__ float g_U[(size_t)KE * DIN];
__device__ int   g_k[BROWS];

// ---------------- arch-feature gate ----------------
#if defined(__CUDA_ARCH_FEAT_SM103_ALL) || defined(__CUDA_ARCH_FAMILY_SPECIFIC__) || defined(__CUDA_ARCH_SPECIFIC__)
#define USE_TC 1
#else
#define USE_TC 0
#endif

// ---------------- common helpers ----------------
__device__ __forceinline__ uint32_t smem_u32(const void* p) {
    uint32_t a;
    asm("{ .reg .u64 t; cvta.to.shared.u64 t, %1; cvt.u32.u64 %0, t; }"
        : "=r"(a) : "l"(p));
    return a;
}
__device__ __forceinline__ float ftr(float x) {
    return __uint_as_float(__float_as_uint(x) & 0xFFFFE000u);
}
#define SW128(o) ((o) ^ (((o) >> 3) & 0x70))

__device__ __forceinline__ void cp16(uint32_t dst, const float* src) {
    asm volatile("cp.async.cg.shared.global [%0], [%1], 16;"
                 :: "r"(dst), "l"((unsigned long long)__cvta_generic_to_global(src))
                 : "memory");
}
__device__ __forceinline__ void cp_commit() {
    asm volatile("cp.async.commit_group;" ::: "memory");
}
__device__ __forceinline__ void cp_wait1() {
    asm volatile("cp.async.wait_group 1;" ::: "memory");
}
__device__ __forceinline__ void cp_wait2() {
    asm volatile("cp.async.wait_group 2;" ::: "memory");
}
__device__ __forceinline__ void mma8(float* c, const uint32_t* a, const uint32_t* b) {
    asm volatile(
        "mma.sync.aligned.m16n8k8.row.col.f32.tf32.tf32.f32 "
        "{%0,%1,%2,%3}, {%4,%5,%6,%7}, {%8,%9}, {%0,%1,%2,%3};\n"
        : "+f"(c[0]), "+f"(c[1]), "+f"(c[2]), "+f"(c[3])
        : "r"(a[0]), "r"(a[1]), "r"(a[2]), "r"(a[3]), "r"(b[0]), "r"(b[1]));
}

#if USE_TC
// ---------------- tcgen05 helpers ----------------
constexpr uint64_t DESC_BASE =
    (uint64_t(2) << 61) | (uint64_t(1) << 46) | (uint64_t(64) << 32) | (uint64_t(1) << 16);
__device__ __forceinline__ uint64_t mkdesc(uint32_t addr) {
    return DESC_BASE | ((uint64_t)(addr >> 4) & 0x3FFF);
}
constexpr uint32_t IDESC_TF32 =
    (1u << 4) | (2u << 7) | (2u << 10) | ((128u / 8) << 17) | ((128u / 16) << 24);
constexpr uint32_t IDESC_TF32_N256 =
    (1u << 4) | (2u << 7) | (2u << 10) | ((256u / 8) << 17) | ((128u / 16) << 24);

__device__ __forceinline__ void mbar_init(uint32_t a, uint32_t cnt) {
    asm volatile("mbarrier.init.shared.b64 [%0], %1;" :: "r"(a), "r"(cnt) : "memory");
}
__device__ __forceinline__ void mbar_arrive(uint32_t a) {
    asm volatile("mbarrier.arrive.shared.b64 _, [%0];" :: "r"(a) : "memory");
}
__device__ __forceinline__ void mbar_wait(uint32_t a, uint32_t ph) {
    asm volatile(
        "{\n\t.reg .pred P;\n\t"
        "W_%=: mbarrier.try_wait.parity.acquire.cta.shared::cta.b64 P, [%0], %1, 0x989680;\n\t"
        "@P bra D_%=;\n\t"
        "bra W_%=;\n\t"
        "D_%=:\n\t}"
        :: "r"(a), "r"(ph) : "memory");
}
__device__ __forceinline__ void tc_alloc(uint32_t dst_smem, uint32_t ncols) {
    asm volatile("tcgen05.alloc.cta_group::1.sync.aligned.shared::cta.b32 [%0], %1;"
                 :: "r"(dst_smem), "r"(ncols) : "memory");
}
__device__ __forceinline__ void tc_relinq() {
    asm volatile("tcgen05.relinquish_alloc_permit.cta_group::1.sync.aligned;");
}
__device__ __forceinline__ void tc_dealloc(uint32_t tmem, uint32_t ncols) {
    asm volatile("tcgen05.dealloc.cta_group::1.sync.aligned.b32 %0, %1;" :: "r"(tmem), "r"(ncols));
}
__device__ __forceinline__ void tc_commit(uint32_t mbar) {
    asm volatile("tcgen05.commit.cta_group::1.mbarrier::arrive::one.shared::cluster.b64 [%0];"
                 :: "r"(mbar) : "memory");
}
__device__ __forceinline__ void mma_tf32i(uint32_t d, uint64_t ad, uint64_t bd,
                                          uint32_t idesc, uint32_t en) {
    asm volatile(
        "{\n\t.reg .pred p;\n\t"
        "setp.ne.u32 p, %4, 0;\n\t"
        "tcgen05.mma.cta_group::1.kind::tf32 [%0], %1, %2, %3, {%5,%5,%5,%5}, p;\n\t}"
        :: "r"(d), "l"(ad), "l"(bd), "r"(idesc), "r"(en), "r"(0u) : "memory");
}
__device__ __forceinline__ void mma_tf32(uint32_t d, uint64_t ad, uint64_t bd, uint32_t en) {
    mma_tf32i(d, ad, bd, IDESC_TF32, en);
}
__device__ __forceinline__ void fence_async() {
    asm volatile("fence.proxy.async.shared::cta;" ::: "memory");
}
__device__ __forceinline__ void tc_fence_after() {
    asm volatile("tcgen05.fence::after_thread_sync;" ::: "memory");
}
__device__ __forceinline__ void tc_wait_ld() {
    asm volatile("tcgen05.wait::ld.sync.aligned;" ::: "memory");
}
__device__ __forceinline__ void ldtm32(uint32_t* r, uint32_t tmem) {
    asm volatile(
        "tcgen05.ld.sync.aligned.32x32b.x32.b32 "
        "{%0,%1,%2,%3,%4,%5,%6,%7,%8,%9,%10,%11,%12,%13,%14,%15,"
        "%16,%17,%18,%19,%20,%21,%22,%23,%24,%25,%26,%27,%28,%29,%30,%31}, [%32];"
        : "=r"(r[0]), "=r"(r[1]), "=r"(r[2]), "=r"(r[3]), "=r"(r[4]), "=r"(r[5]),
          "=r"(r[6]), "=r"(r[7]), "=r"(r[8]), "=r"(r[9]), "=r"(r[10]), "=r"(r[11]),
          "=r"(r[12]), "=r"(r[13]), "=r"(r[14]), "=r"(r[15]), "=r"(r[16]), "=r"(r[17]),
          "=r"(r[18]), "=r"(r[19]), "=r"(r[20]), "=r"(r[21]), "=r"(r[22]), "=r"(r[23]),
          "=r"(r[24]), "=r"(r[25]), "=r"(r[26]), "=r"(r[27]), "=r"(r[28]), "=r"(r[29]),
          "=r"(r[30]), "=r"(r[31])
        : "r"(tmem));
}
#endif  // USE_TC

// ---------------- smem geometry ----------------
// 512-thread z_e / U kernel (R13 geometry)
constexpr int NSTAGE3 = 3;
constexpr int STG_STRIDE = 132;
constexpr int STG_BYTES  = 32 * STG_STRIDE * 4;   // 16896
constexpr int GSMEM3 = 217088;
// 288-thread dist kernel
constexpr int GSMEM1 = 73728;
// N256 x_e kernel
constexpr int NSTR256 = 260;
constexpr int NSTG256 = 32 * NSTR256 * 4;     // 33280
constexpr int GSMEMN = 2048 + 2 * 65536 + 2 * NSTG256;   // 199680

// fallback smem constants
constexpr int ASTR  = 36;
constexpr int BSTR0 = 136;
constexpr int ABYTES = 128 * ASTR * 4;
constexpr int STAGE  = ABYTES + 18432;

// =====================================================================
// gemm_any: 512 threads, 1 CTA/SM, 3-pass (z_e, U) — R15 verbatim
// =====================================================================
template <int MODE, int NPASS>
__global__ __launch_bounds__(512, 1) void gemm_any(
    const float* __restrict__ A, const float* __restrict__ B,
    const float* __restrict__ bias, float* __restrict__ C,
    int M, int N, int K)
{
#if USE_TC
    constexpr int NBUF = 2;
    constexpr int BUFB = 65536;
    constexpr int ALO  = 16384;
    constexpr int BHI  = 32768;

    extern __shared__ char smem[];
    const uint32_t sb = smem_u32(smem);
    const uint32_t ab0 = (sb + 1152u) & ~1023u;
    char* const base = smem + (ab0 - sb);
    const uint32_t stg_u = ab0 + NBUF * BUFB;
    char* const stg = base + NBUF * BUFB;

    const int tid = threadIdx.x, lane = tid & 31, warp = tid >> 5;
    const int m0 = blockIdx.y * 128, n0 = blockIdx.x * 128;

    const uint32_t FUL = sb + 8, EMP = sb + 48, DON = sb + 88;

    if (warp == 0) { tc_alloc(sb, 128); tc_relinq(); }
    if (tid == 0) {
#pragma unroll
        for (int s = 0; s < NBUF; s++) {
            mbar_init(FUL + s * 8, 8);
            mbar_init(EMP + s * 8, 1);
        }
        mbar_init(DON, 1);
    }
    __syncthreads();
    const uint32_t tmem = *(const uint32_t*)smem;
    const int nch = K / 32;

    if (tid < 256) {
        const int arow = tid >> 1, acolb = (tid & 1) * 16;
        const int krow = tid >> 3, nseg = (tid & 7) * 16;
        const int bn = tid & 127, khalf = tid >> 7;

        float4 a0[4], a1[4], b0[4], b1[4];

        auto fetchA = [&](int c, float4 (&ar)[4], float4 (&br)[4]) {
            const float* ap = A + (size_t)(m0 + arow) * K + c * 32 + acolb;
#pragma unroll
            for (int q = 0; q < 4; q++) ar[q] = *(const float4*)(ap + q * 4);
            if (MODE == 1) {
                const float* bp = B + (size_t)(n0 + arow) * K + c * 32 + acolb;
#pragma unroll
                for (int q = 0; q < 4; q++) br[q] = *(const float4*)(bp + q * 4);
            }
        };
        auto issueB = [&](int c) {
            const uint32_t d = stg_u + (c & 3) * STG_BYTES + (krow * STG_STRIDE + nseg) * 4;
            const float* src = B + (size_t)(c * 32 + krow) * N + n0 + nseg;
#pragma unroll
            for (int j = 0; j < 4; j++) cp16(d + j * 16, src + j * 4);
        };

        auto chunk = [&](int c, float4 (&ar)[4], float4 (&br)[4]) {
            const int s = c % NBUF;
            char* AHp = base + s * BUFB;
            if (c >= NBUF)
                mbar_wait(EMP + s * 8, (uint32_t)((c / NBUF - 1) & 1));

            if (MODE == 0) {
                cp_wait2();
                asm volatile("bar.sync 1, 256;" ::: "memory");
                if (c + 3 < nch) issueB(c + 3);
                cp_commit();
                const float* sg = (const float*)(stg + (c & 3) * STG_BYTES);
                float bv[16];
#pragma unroll
                for (int j = 0; j < 16; j++)
                    bv[j] = sg[(khalf * 16 + j) * STG_STRIDE + bn];
#pragma unroll
                for (int q = 0; q < 4; q++) {
                    const uint32_t off = (uint32_t)(bn * 128 + khalf * 64 + q * 16);
                    float4 v = *(float4*)&bv[q * 4];
                    float4 h, l;
                    h.x = ftr(v.x); h.y = ftr(v.y); h.z = ftr(v.z); h.w = ftr(v.w);
                    l.x = v.x - h.x; l.y = v.y - h.y; l.z = v.z - h.z; l.w = v.w - h.w;
                    *(float4*)(AHp + BHI + SW128(off)) = h;
                    *(float4*)(AHp + BHI + 16384 + SW128(off)) = l;
                }
            }

#pragma unroll
            for (int q = 0; q < 4; q++) {
                float4 v = ar[q];
                const uint32_t sw = SW128((uint32_t)(arow * 128 + acolb * 4 + q * 16));
                float4 h, l;
                h.x = ftr(v.x); h.y = ftr(v.y); h.z = ftr(v.z); h.w = ftr(v.w);
                l.x = v.x - h.x; l.y = v.y - h.y; l.z = v.z - h.z; l.w = v.w - h.w;
                *(float4*)(AHp + sw) = h;
                *(float4*)(AHp + ALO + sw) = l;
            }
            if (MODE == 1) {
#pragma unroll
                for (int q = 0; q < 4; q++) {
                    float4 v = br[q];
                    const uint32_t sw = SW128((uint32_t)(arow * 128 + acolb * 4 + q * 16));
                    float4 h, l;
                    h.x = ftr(v.x); h.y = ftr(v.y); h.z = ftr(v.z); h.w = ftr(v.w);
                    l.x = v.x - h.x; l.y = v.y - h.y; l.z = v.z - h.z; l.w = v.w - h.w;
                    *(float4*)(AHp + BHI + sw) = h;
                    *(float4*)(AHp + BHI + 16384 + sw) = l;
                }
            }
            if (c + 2 < nch) fetchA(c + 2, ar, br);
            fence_async();
            __syncwarp();
            if (lane == 0) mbar_arrive(FUL + s * 8);
        };

        fetchA(0, a0, b0);
        fetchA(1, a1, b1);
        if (MODE == 0) {
            issueB(0); cp_commit();
            issueB(1); cp_commit();
            issueB(2); cp_commit();
        }
        for (int c = 0; c < nch; c += 2) {
            chunk(c, a0, b0);
            chunk(c + 1, a1, b1);
        }
    } else if (tid == 256) {
        for (int c = 0; c < nch; c++) {
            const int s = c % NBUF;
            mbar_wait(FUL + s * 8, (uint32_t)((c / NBUF) & 1));
            const uint32_t AHu = ab0 + s * BUFB;
            const uint64_t adh = mkdesc(AHu), adl = mkdesc(AHu + ALO);
            const uint64_t bdh = mkdesc(AHu + BHI), bdl = mkdesc(AHu + BHI + 16384);
#pragma unroll
            for (int ks = 0; ks < 4; ks++) {
                const uint64_t o = ks * 2;
                const uint32_t en0 = (c == 0 && ks == 0) ? 0u : 1u;
                mma_tf32(tmem, adh + o, bdl + o, en0);
                mma_tf32(tmem, adl + o, bdh + o, 1u);
                mma_tf32(tmem, adh + o, bdh + o, 1u);
            }
            tc_commit(c == nch - 1 ? DON : (EMP + s * 8));
        }
    }

    mbar_wait(DON, 0u);
    tc_fence_after();

    if (warp < 4) {
        const int row = m0 + warp * 32 + lane;
#pragma unroll
        for (int half = 0; half < 2; half++) {
            uint32_t r[64];
            ldtm32(r, tmem + half * 64);
            ldtm32(r + 32, tmem + half * 64 + 32);
            tc_wait_ld();
            float* dst = C + (size_t)row * N + n0 + half * 64;
            if (MODE == 0) {
                const float4* b4 = (const float4*)(bias + n0 + half * 64);
#pragma unroll
                for (int q = 0; q < 16; q++) {
                    float4 b = b4[q];
                    float4 v;
                    v.x = __uint_as_float(r[q * 4 + 0]) + b.x;
                    v.y = __uint_as_float(r[q * 4 + 1]) + b.y;
                    v.z = __uint_as_float(r[q * 4 + 2]) + b.z;
                    v.w = __uint_as_float(r[q * 4 + 3]) + b.w;
                    *(float4*)(dst + q * 4) = v;
                }
            } else {
                const float zs = g_zsq[row];
                const float4* e4 = (const float4*)(g_esq + n0 + half * 64);
#pragma unroll
                for (int q = 0; q < 16; q++) {
                    float4 e = e4[q];
                    float4 v;
                    v.x = (zs - 2.f * __uint_as_float(r[q * 4 + 0])) + e.x;
                    v.y = (zs - 2.f * __uint_as_float(r[q * 4 + 1])) + e.y;
                    v.z = (zs - 2.f * __uint_as_float(r[q * 4 + 2])) + e.z;
                    v.w = (zs - 2.f * __uint_as_float(r[q * 4 + 3])) + e.w;
                    *(float4*)(dst + q * 4) = v;
                }
            }
        }
    }
    __syncthreads();
    if (warp == 0) tc_dealloc(tmem, 128);

#else
    // ---- fallback (mma.sync; never runs on sm_103a target) ----
    extern __shared__ char smem[];
    const uint32_t sb = smem_u32(smem);
    const int tid = threadIdx.x, lane = tid & 31, warp = tid >> 5;
    const int wm = warp >> 2, wn = warp & 3;
    const int rq = lane >> 2, cq = lane & 3;
    const int m0 = blockIdx.y * 128, n0 = blockIdx.x * 128;
    const int lrow = tid >> 2, lcs = (tid & 3) * 8;
    const int krow = tid >> 4, nseg = (tid & 15) * 8;

    float acc[2][4][4];
#pragma unroll
    for (int mt = 0; mt < 2; mt++)
#pragma unroll
        for (int nt = 0; nt < 4; nt++)
#pragma unroll
            for (int r = 0; r < 4; r++) acc[mt][nt][r] = 0.f;

    const int nch = K / 32;
    auto issue = [&](int c) {
        const int k0 = c * 32, buf = c % NSTAGE3;
        const uint32_t ab = sb + buf * STAGE;
        const uint32_t bb = ab + ABYTES;
        const float* asrc = A + (size_t)(m0 + lrow) * K + k0 + lcs;
        cp16(ab + (lrow * ASTR + lcs) * 4, asrc);
        cp16(ab + (lrow * ASTR + lcs + 4) * 4, asrc + 4);
        if (MODE == 0) {
            const float* bsrc = B + (size_t)(k0 + krow) * N + n0 + nseg;
            cp16(bb + (krow * BSTR0 + nseg) * 4, bsrc);
            cp16(bb + (krow * BSTR0 + nseg + 4) * 4, bsrc + 4);
        } else {
            const float* bsrc = B + (size_t)(n0 + lrow) * K + k0 + lcs;
            cp16(bb + (lrow * ASTR + lcs) * 4, bsrc);
            cp16(bb + (lrow * ASTR + lcs + 4) * 4, bsrc + 4);
        }
        cp_commit();
    };

    issue(0);
    if (nch > 1) issue(1);
    for (int c = 0; c < nch; c++) {
        cp_wait1();
        __syncthreads();
        if (c + 2 < nch) issue(c + 2);
        const int buf = c % NSTAGE3;
        const uint32_t* As = (const uint32_t*)(smem + buf * STAGE);
        const uint32_t* Bs = (const uint32_t*)(smem + buf * STAGE + ABYTES);
#pragma unroll
        for (int ks = 0; ks < 32; ks += 8) {
            uint32_t a[2][4], b[4][2];
#pragma unroll
            for (int mt = 0; mt < 2; mt++) {
                const int r0 = (wm * 32 + mt * 16 + rq) * ASTR + ks + cq;
                a[mt][0] = As[r0];
                a[mt][1] = As[r0 + 8 * ASTR];
                a[mt][2] = As[r0 + 4];
                a[mt][3] = As[r0 + 8 * ASTR + 4];
            }
#pragma unroll
            for (int nt = 0; nt < 4; nt++) {
                const int n = wn * 32 + nt * 8 + rq;
                if (MODE == 0) {
                    b[nt][0] = Bs[(ks + cq) * BSTR0 + n];
                    b[nt][1] = Bs[(ks + cq + 4) * BSTR0 + n];
                } else {
                    b[nt][0] = Bs[n * ASTR + ks + cq];
                    b[nt][1] = Bs[n * ASTR + ks + cq + 4];
                }
            }
            uint32_t ah[2][4], al[2][4], bh[4][2], bl[4][2];
#pragma unroll
            for (int mt = 0; mt < 2; mt++)
#pragma unroll
                for (int r = 0; r < 4; r++) {
                    ah[mt][r] = a[mt][r] & 0xFFFFE000u;
                    al[mt][r] = __float_as_uint(
                        __uint_as_float(a[mt][r]) - __uint_as_float(ah[mt][r]));
                }
#pragma unroll
            for (int nt = 0; nt < 4; nt++)
#pragma unroll
                for (int r = 0; r < 2; r++) {
                    bh[nt][r] = b[nt][r] & 0xFFFFE000u;
                    bl[nt][r] = __float_as_uint(
                        __uint_as_float(b[nt][r]) - __uint_as_float(bh[nt][r]));
                }
#pragma unroll
            for (int mt = 0; mt < 2; mt++)
#pragma unroll
                for (int nt = 0; nt < 4; nt++) {
                    mma8(acc[mt][nt], ah[mt], bl[nt]);
                    mma8(acc[mt][nt], al[mt], bh[nt]);
                    mma8(acc[mt][nt], ah[mt], bh[nt]);
                }
        }
    }
#pragma unroll
    for (int mt = 0; mt < 2; mt++) {
        const int row = m0 + wm * 32 + mt * 16 + rq;
#pragma unroll
        for (int nt = 0; nt < 4; nt++) {
            const int col = n0 + wn * 32 + nt * 8 + 2 * cq;
            float* c = acc[mt][nt];
            if (MODE == 0) {
                const float b0 = bias[col], b1 = bias[col + 1];
                *(float2*)&C[(size_t)row * N + col] = make_float2(c[0] + b0, c[1] + b1);
                *(float2*)&C[(size_t)(row + 8) * N + col] = make_float2(c[2] + b0, c[3] + b1);
            } else {
                const float zs0 = g_zsq[row], zs1 = g_zsq[row + 8];
                const float e0 = g_esq[col], e1 = g_esq[col + 1];
                *(float2*)&C[(size_t)row * N + col] =
                    make_float2((zs0 - 2.f * c[0]) + e0, (zs0 - 2.f * c[1]) + e1);
                *(float2*)&C[(size_t)(row + 8) * N + col] =
                    make_float2((zs1 - 2.f * c[2]) + e0, (zs1 - 2.f * c[3]) + e1);
            }
        }
    }
#endif
}

// =====================================================================
// gemm_n256: 128x256 tile, 2-pass (split A), staged B. x_e only — R15 verbatim
// =====================================================================
__global__ __launch_bounds__(544, 1) void gemm_n256(
    const float* __restrict__ A, const float* __restrict__ B,
    const float* __restrict__ bias, float* __restrict__ C,
    int M, int N, int K)
{
#if USE_TC
    constexpr int NBUF = 2;
    constexpr int BUFB = 65536;
    constexpr int ALO  = 16384;
    constexpr int BHI  = 32768;

    extern __shared__ char smem[];
    const uint32_t sb = smem_u32(smem);
    const uint32_t ab0 = (sb + 1152u) & ~1023u;
    char* const base = smem + (ab0 - sb);
    const uint32_t stg_u = ab0 + NBUF * BUFB;
    char* const stg = base + NBUF * BUFB;

    const int tid = threadIdx.x, lane = tid & 31, warp = tid >> 5;
    const int m0 = blockIdx.y * 128, n1 = blockIdx.x * 256;

    const uint32_t FUL = sb + 8, EMP = sb + 24, DON = sb + 40;

    if (warp == 0) { tc_alloc(sb, 256); tc_relinq(); }
    if (tid == 0) {
#pragma unroll
        for (int s = 0; s < NBUF; s++) {
            mbar_init(FUL + s * 8, 16);
            mbar_init(EMP + s * 8, 1);
        }
        mbar_init(DON, 1);
    }
    __syncthreads();
    const uint32_t tmem = *(const uint32_t*)smem;
    const int nch = K / 32;

    if (tid < 512) {
        const int arow = tid >> 2, acolb = (tid & 3) * 8;
        const int krow = tid >> 4, nseg = (tid & 15) * 16;
        const int bn = tid & 255, kq = tid >> 8;

        float4 a0[2], a1[2];

        auto fetchA = [&](int c, float4 (&ar)[2]) {
            const float* ap = A + (size_t)(m0 + arow) * K + c * 32 + acolb;
            ar[0] = *(const float4*)ap;
            ar[1] = *(const float4*)(ap + 4);
        };
        auto issueB = [&](int c) {
            const uint32_t d = stg_u + (c & 1) * NSTG256 + (krow * NSTR256 + nseg) * 4;
            const float* src = B + (size_t)(c * 32 + krow) * N + n1 + nseg;
#pragma unroll
            for (int j = 0; j < 4; j++) cp16(d + j * 16, src + j * 4);
        };

        fetchA(0, a0);
        if (nch > 1) fetchA(1, a1);
        issueB(0); cp_commit();
        if (nch > 1) { issueB(1); cp_commit(); }

        for (int c = 0; c < nch; c++) {
            const int s = c & 1;
            char* const AHp = base + s * BUFB;
            if (c >= NBUF) mbar_wait(EMP + s * 8, (uint32_t)((c / NBUF - 1) & 1));

            cp_wait1();
            asm volatile("bar.sync 1, 512;" ::: "memory");

            const float* sg = (const float*)(stg + (c & 1) * NSTG256);
            float bv[16];
#pragma unroll
            for (int j = 0; j < 16; j++)
                bv[j] = sg[(kq * 16 + j) * NSTR256 + bn];

            asm volatile("bar.sync 1, 512;" ::: "memory");
            if (c + 2 < nch) issueB(c + 2);
            cp_commit();

#pragma unroll
            for (int q = 0; q < 4; q++) {
                const uint32_t off = (uint32_t)(bn * 128 + kq * 64 + q * 16);
                *(float4*)(AHp + BHI + SW128(off)) = *(float4*)&bv[q * 4];
            }

            float4* const asrc = (c & 1) ? a1 : a0;
#pragma unroll
            for (int q = 0; q < 2; q++) {
                float4 v = asrc[q];
                const uint32_t sw = SW128((uint32_t)(arow * 128 + (acolb + q * 4) * 4));
                float4 h, l;
                h.x = ftr(v.x); h.y = ftr(v.y); h.z = ftr(v.z); h.w = ftr(v.w);
                l.x = v.x - h.x; l.y = v.y - h.y; l.z = v.z - h.z; l.w = v.w - h.w;
                *(float4*)(AHp + sw) = h;
                *(float4*)(AHp + ALO + sw) = l;
            }

            if (c + 2 < nch) fetchA(c + 2, (c & 1) ? a1 : a0);
            fence_async();
            __syncwarp();
            if (lane == 0) mbar_arrive(FUL + s * 8);
        }
    } else if (tid == 512) {
        for (int c = 0; c < nch; c++) {
            const int s = c & 1;
            mbar_wait(FUL + s * 8, (uint32_t)((c / NBUF) & 1));
            const uint32_t AHu = ab0 + s * BUFB;
            const uint64_t adh = mkdesc(AHu), adl = mkdesc(AHu + ALO);
            const uint64_t bdh = mkdesc(AHu + BHI);
#pragma unroll
            for (int ks = 0; ks < 4; ks++) {
                const uint64_t o = ks * 2;
                const uint32_t en0 = (c == 0 && ks == 0) ? 0u : 1u;
                mma_tf32i(tmem, adl + o, bdh + o, IDESC_TF32_N256, en0);
                mma_tf32i(tmem, adh + o, bdh + o, IDESC_TF32_N256, 1u);
            }
            tc_commit(c == nch - 1 ? DON : (EMP + s * 8));
        }
    }

    mbar_wait(DON, 0u);
    tc_fence_after();

    if (warp < 4) {
        const int row = m0 + warp * 32 + lane;
#pragma unroll
        for (int cb = 0; cb < 256; cb += 32) {
            uint32_t r[32];
            ldtm32(r, tmem + cb);
            tc_wait_ld();
            float* dst = C + (size_t)row * N + n1 + cb;
            const float4* b4 = (const float4*)(bias + n1 + cb);
#pragma unroll
            for (int q = 0; q < 8; q++) {
                float4 b = b4[q];
                float4 v;
                v.x = __uint_as_float(r[q * 4 + 0]) + b.x;
                v.y = __uint_as_float(r[q * 4 + 1]) + b.y;
                v.z = __uint_as_float(r[q * 4 + 2]) + b.z;
                v.w = __uint_as_float(r[q * 4 + 3]) + b.w;
                *(float4*)(dst + q * 4) = v;
            }
        }
    }
    __syncthreads();
    if (warp == 0) tc_dealloc(tmem, 256);

#else
    const int tid = threadIdx.x;
    const int m0 = blockIdx.y * 128, n1 = blockIdx.x * 256;
    for (int idx = tid; idx < 128 * 256; idx += 544) {
        const int m = m0 + (idx >> 8);
        const int n = n1 + (idx & 255);
        float s = 0.f;
        const float* a = A + (size_t)m * K;
        for (int k = 0; k < K; k++) s = fmaf(a[k], B[(size_t)k * N + n], s);
        C[(size_t)m * N + n] = s + bias[n];
    }
#endif
}

// =====================================================================
// gemm_dist: 288 threads, 2 CTA/SM, 1-pass — R15 verbatim
// =====================================================================
__global__ __launch_bounds__(288, 2) void gemm_dist(
    const float* __restrict__ A, const float* __restrict__ B,
    float* __restrict__ C, int M, int N, int K)
{
#if USE_TC
    constexpr int NBUF = 2;
    constexpr int BUFB = 32768;
    constexpr int BHI  = 16384;

    extern __shared__ char smem[];
    const uint32_t sb = smem_u32(smem);
    const uint32_t ab0 = (sb + 1152u) & ~1023u;
    char* const base = smem + (ab0 - sb);

    const int tid = threadIdx.x, lane = tid & 31, warp = tid >> 5;
    const int m0 = blockIdx.y * 128, n0 = blockIdx.x * 128;

    const uint32_t FUL = sb + 8, EMP = sb + 24, DON = sb + 40;

    if (warp == 0) { tc_alloc(sb, 128); tc_relinq(); }
    if (tid == 0) {
#pragma unroll
        for (int s = 0; s < NBUF; s++) {
            mbar_init(FUL + s * 8, 8);
            mbar_init(EMP + s * 8, 1);
        }
        mbar_init(DON, 1);
    }
    __syncthreads();
    const uint32_t tmem = *(const uint32_t*)smem;
    const int nch = K / 32;

    if (tid < 256) {
        const int arow = tid >> 1, acolb = (tid & 1) * 16;
        float4 ar[2][4], br[2][4];

        auto fetch = [&](int c, int s) {
            const float* ap = A + (size_t)(m0 + arow) * K + c * 32 + acolb;
#pragma unroll
            for (int q = 0; q < 4; q++) ar[s][q] = *(const float4*)(ap + q * 4);
            const float* bp = B + (size_t)(n0 + arow) * K + c * 32 + acolb;
#pragma unroll
            for (int q = 0; q < 4; q++) br[s][q] = *(const float4*)(bp + q * 4);
        };

        fetch(0, 0);
        if (nch > 1) fetch(1, 1);

        for (int c = 0; c < nch; c++) {
            const int s = c & 1;
            char* const AHp = base + s * BUFB;
            if (c >= NBUF) mbar_wait(EMP + s * 8, (uint32_t)((c / NBUF - 1) & 1));

#pragma unroll
            for (int q = 0; q < 4; q++) {
                const uint32_t sw = SW128((uint32_t)(arow * 128 + acolb * 4 + q * 16));
                *(float4*)(AHp + BHI + sw) = br[s][q];
                *(float4*)(AHp + sw) = ar[s][q];
            }
            if (c + 2 < nch) fetch(c + 2, s);
            fence_async();
            __syncwarp();
            if (lane == 0) mbar_arrive(FUL + s * 8);
        }
    } else if (tid == 256) {
        for (int c = 0; c < nch; c++) {
            const int s = c & 1;
            mbar_wait(FUL + s * 8, (uint32_t)((c / NBUF) & 1));
            const uint32_t AHu = ab0 + s * BUFB;
            const uint64_t adh = mkdesc(AHu), bdh = mkdesc(AHu + BHI);
#pragma unroll
            for (int ks = 0; ks < 4; ks++) {
                const uint64_t o = ks * 2;
                mma_tf32(tmem, adh + o, bdh + o, (c == 0 && ks == 0) ? 0u : 1u);
            }
            tc_commit(c == nch - 1 ? DON : (EMP + s * 8));
        }
    }

    mbar_wait(DON, 0u);
    tc_fence_after();

    if (warp < 4) {
        const int row = m0 + warp * 32 + lane;
#pragma unroll
        for (int cb = 0; cb < 128; cb += 32) {
            uint32_t r[32];
            ldtm32(r, tmem + cb);
            tc_wait_ld();
            float* dst = C + (size_t)row * N + n0 + cb;
            const float zs = g_zsq[row];
            const float4* e4 = (const float4*)(g_esq + n0 + cb);
#pragma unroll
            for (int q = 0; q < 8; q++) {
                float4 e = e4[q];
                float4 v;
                v.x = (zs - 2.f * __uint_as_float(r[q * 4 + 0])) + e.x;
                v.y = (zs - 2.f * __uint_as_float(r[q * 4 + 1])) + e.y;
                v.z = (zs - 2.f * __uint_as_float(r[q * 4 + 2])) + e.z;
                v.w = (zs - 2.f * __uint_as_float(r[q * 4 + 3])) + e.w;
                *(float4*)(dst + q * 4) = v;
            }
        }
    }
    __syncthreads();
    if (warp == 0) tc_dealloc(tmem, 128);

#else
    const int tid = threadIdx.x;
    const int m0 = blockIdx.y * 128, n0 = blockIdx.x * 128;
    for (int idx = tid; idx < 128 * 128; idx += 288) {
        const int m = m0 + (idx >> 7);
        const int n = n0 + (idx & 127);
        float t = 0.f;
        const float* a = A + (size_t)m * K;
        const float* b = B + (size_t)n * K;
        for (int k = 0; k < K; k++) t = fmaf(a[k], b[k], t);
        C[(size_t)m * N + n] = (g_zsq[m] - 2.f * t) + g_esq[n];
    }
#endif
}

// ---------------- rowsq: float4 loads, 4 independent fp64 chains ----------------
__global__ void rowsq_kernel(const float* __restrict__ Z, float* __restrict__ out,
                             int rows, int cols)
{
    int row = blockIdx.x * (blockDim.x >> 5) + (threadIdx.x >> 5);
    int lane = threadIdx.x & 31;
    if (row >= rows) return;
    const float4* z = (const float4*)(Z + (size_t)row * cols);
    const int nf4 = cols >> 2;
    double s0 = 0.0, s1 = 0.0, s2 = 0.0, s3 = 0.0;
    for (int f = lane; f < nf4; f += 32) {
        float4 v = z[f];
        s0 += (double)v.x * (double)v.x;
        s1 += (double)v.y * (double)v.y;
        s2 += (double)v.z * (double)v.z;
        s3 += (double)v.w * (double)v.w;
    }
    double s = (s0 + s1) + (s2 + s3);
#pragma unroll
    for (int o = 16; o > 0; o >>= 1) s += __shfl_xor_sync(0xffffffffu, s, o);
    if (lane == 0) out[row] = (float)s;
}

// ---------------- fused top-4 (warp-register) + fp64 refine -> k ----------------
__global__ __launch_bounds__(128) void refine_kernel(
    const float* __restrict__ dist, const float* __restrict__ ZE,
    const float* __restrict__ emb, float* __restrict__ out)
{
    const int row = blockIdx.x;
    const int t = threadIdx.x;
    const int w = t >> 5;
    const int lane = t & 31;

    __shared__ int   cand4[4];
    __shared__ float cv[4];
    __shared__ int   ci[4];

    if (w == 0) {
        // warp-register top-4 (R7 semantics: first-occurrence min)
        float d[8];
        const float4* src = (const float4*)(dist + (size_t)row * KE + lane * 8);
        float4 v0 = src[0], v1 = src[1];
        d[0] = v0.x; d[1] = v0.y; d[2] = v0.z; d[3] = v0.w;
        d[4] = v1.x; d[5] = v1.y; d[6] = v1.z; d[7] = v1.w;

#pragma unroll
        for (int r = 0; r < 4; r++) {
            float bv = d[0];
            int   bj = 0;
#pragma unroll
            for (int j = 1; j < 8; j++)
                if (d[j] < bv) { bv = d[j]; bj = j; }
            int bi = lane * 8 + bj;
#pragma unroll
            for (int o = 16; o > 0; o >>= 1) {
                float ov = __shfl_xor_sync(0xffffffffu, bv, o);
                int   oi = __shfl_xor_sync(0xffffffffu, bi, o);
                if (ov < bv || (ov == bv && oi < bi)) { bv = ov; bi = oi; }
            }
            if (lane == 0) cand4[r] = bi;
            if ((bi >> 3) == lane) d[bi & 7] = CUDART_INF_F;
        }
    }
    __syncthreads();

    const int cand = cand4[w];
    const float* z = ZE + (size_t)row * LAT;
    const float* e = emb + (size_t)cand * LAT;

    double s = 0.0;
    for (int j = lane; j < LAT; j += 32)
        s += (double)z[j] * (double)e[j];
#pragma unroll
    for (int o = 16; o > 0; o >>= 1) s += __shfl_xor_sync(0xffffffffu, s, o);

    if (lane == 0) {
        float tt = (float)s;
        float a = g_zsq[row] - 2.f * tt;
        float d = a + g_esq[cand];
        cv[w] = d;
        ci[w] = cand;
    }
    __syncthreads();

    if (t == 0) {
        float bv = cv[0]; int bi = ci[0];
#pragma unroll
        for (int r = 1; r < 4; r++) {
            float v = cv[r]; int i = ci[r];
            if (v < bv || (v == bv && i < bi)) { bv = v; bi = i; }
        }
        g_k[row] = bi;
        out[OFF_K + row] = (float)bi;
    }
}

// ---------------- fused gathers (float4): z_q, neighbors, x_q ----------------
__global__ __launch_bounds__(128) void gather_all_kernel(
    const float* __restrict__ emb, float* __restrict__ out)
{
    const int row = blockIdx.x;
    const int t = threadIdx.x;
    const int k = g_k[row];

    const int k1 = k / SOMW;
    const int k2 = k % SOMW;
    const float4* s0 = (const float4*)(emb + (size_t)k * LAT);
    const float4* s1 = (k1 < SOMW - 1) ? (const float4*)(emb + (size_t)(k + SOMW) * LAT) : nullptr;
    const float4* s2 = (k1 > 0)        ? (const float4*)(emb + (size_t)(k - SOMW) * LAT) : nullptr;
    const float4* s4 = (k2 > 0)        ? (const float4*)(emb + (size_t)(k - 1) * LAT)    : nullptr;
    const float4 zero = make_float4(0.f, 0.f, 0.f, 0.f);

    float4* zq = (float4*)(out + OFF_ZQ + (size_t)row * LAT);
    float4* nb = (float4*)(out + OFF_NB + (size_t)row * 5 * LAT);

    float4 v0 = s0[t];
    zq[t] = v0;
    nb[t] = v0;
    nb[128 + t] = s1 ? s1[t] : zero;
    nb[256 + t] = s2 ? s2[t] : zero;
    nb[384 + t] = zero;                  // right (faithful bug: always 0)
    nb[512 + t] = s4 ? s4[t] : zero;

    const float4* us = (const float4*)(g_U + (size_t)k * DIN);
    float4* xq = (float4*)(out + OFF_XQ + (size_t)row * DIN);
#pragma unroll
    for (int i = t; i < DIN / 4; i += 128)
        xq[i] = us[i];
}

// =====================================================================
extern "C" void kernel_launch(void* const* d_in, const int* in_sizes, int n_in,
                              void* d_out, int out_size)
{
    const float* x       = (const float*)d_in[0];
    const float* enc_w   = (const float*)d_in[1];
    const float* enc_b   = (const float*)d_in[2];
    const float* dec_q_w = (const float*)d_in[3];
    const float* dec_q_b = (const float*)d_in[4];
    const float* dec_e_w = (const float*)d_in[5];
    const float* dec_e_b = (const float*)d_in[6];
    const float* emb     = (const float*)d_in[7];
    float* out = (float*)d_out;

    float* zsq_p; cudaGetSymbolAddress((void**)&zsq_p, g_zsq);
    float* esq_p; cudaGetSymbolAddress((void**)&esq_p, g_esq);
    float* U_p;   cudaGetSymbolAddress((void**)&U_p,   g_U);

    cudaFuncSetAttribute(gemm_any<0, 3>, cudaFuncAttributeMaxDynamicSharedMemorySize, GSMEM3);
    cudaFuncSetAttribute(gemm_n256, cudaFuncAttributeMaxDynamicSharedMemorySize, GSMEMN);
    cudaFuncSetAttribute(gemm_dist, cudaFuncAttributeMaxDynamicSharedMemorySize, GSMEM1);

    // launch 0: e_sq
    rowsq_kernel<<<KE / 8, 256>>>(emb, esq_p, KE, LAT);

    // launch 1: z_e = x @ enc_w + enc_b   (3-pass, fp32-grade, bit-stable)
    gemm_any<0, 3><<<dim3(LAT / 128, BROWS / 128), 512, GSMEM3>>>(
        x, enc_w, enc_b, out + OFF_ZE, BROWS, LAT, DIN);

    // launch 2: z_sq
    rowsq_kernel<<<BROWS / 8, 256>>>(out + OFF_ZE, zsq_p, BROWS, LAT);

    // launch 3 (ncu capture slot): x_e (2-pass, 128x256 tile)
    gemm_n256<<<dim3(DIN / 256, BROWS / 128), 544, GSMEMN>>>(
        out + OFF_ZE, dec_e_w, dec_e_b, out + OFF_XE, BROWS, DIN, LAT);

    // launch 4: U = emb_flat @ dec_q_w + dec_q_b   (3-pass, tiny)
    gemm_any<0, 3><<<dim3(DIN / 128, KE / 128), 512, GSMEM3>>>(
        emb, dec_q_w, dec_q_b, U_p, KE, DIN, LAT);

    // launch 5: z_dist_flat (1-pass, 2 CTA/SM; argmin protected by refine)
    gemm_dist<<<dim3(KE / 128, BROWS / 128), 288, GSMEM1>>>(
        out + OFF_ZE, emb, out + OFF_DIST, BROWS, KE, LAT);

    // launch 6: fused warp top-4 + fp64 refine -> k
    refine_kernel<<<BROWS, 128>>>(out + OFF_DIST, out + OFF_ZE, emb, out);

    // launch 7: fused gathers (float4)
    gather_all_kernel<<<BROWS, 128>>>(emb, out);
}